// round 7
// baseline (speedup 1.0000x reference)
#include <cuda_runtime.h>
#include <cstddef>

// SelfAttention: out = softmax(Q K^T / sqrt(D) + bias, mask) @ V
// Shapes (hardcoded per reference): B=4, H=16, L=2048, D=64, all fp32.
// SIMT fp32 flash-attention baseline: 128q x 64k tiles, 8x4 register micro-tiles,
// transposed smem staging for conflict-free operand loads, log2-domain online softmax.

#define B_  4
#define H_  16
#define L_  2048
#define D_  64
#define BQ  128
#define BK  64
#define NKT (L_ / BK)   // 32
#define NQT (L_ / BQ)   // 16

// smem strides (floats). Odd 65 for scalar-store transpose (2-way max conflict);
// 132 (=33*4) keeps float4 alignment with tx-spread bank mapping.
#define QS_STR 132
#define KS_STR 65
#define VS_STR 64
#define PS_STR 132

#define OFF_QST 0
#define OFF_KST (OFF_QST + 64 * QS_STR)     // 8448
#define OFF_VS  (OFF_KST + 64 * KS_STR)     // 12608
#define OFF_PST (OFF_VS  + BK * VS_STR)     // 16704
#define SMEM_FLOATS (OFF_PST + BK * PS_STR) // 25152
#define SMEM_BYTES  (SMEM_FLOATS * 4)       // 100608

__device__ __forceinline__ float ex2f(float x) {
    float y;
    asm("ex2.approx.ftz.f32 %0, %1;" : "=f"(y) : "f"(x));
    return y;
}

extern __shared__ float sm_dyn[];

__global__ __launch_bounds__(256, 2)
void SelfAttention_53369263620701_kernel(
    const float* __restrict__ Q, const float* __restrict__ K,
    const float* __restrict__ V, const int* __restrict__ AM,
    const float* __restrict__ BIAS, float* __restrict__ OUT)
{
    float* QsT = sm_dyn + OFF_QST;  // [d][q]   d:64, q:128 (stride 132)
    float* KsT = sm_dyn + OFF_KST;  // [d][k]   d:64, k:64  (stride 65)
    float* Vs  = sm_dyn + OFF_VS;   // [k][d]   k:64, d:64  (stride 64)
    float* PsT = sm_dyn + OFF_PST;  // [k][q]   k:64, q:128 (stride 132)

    const int tid = threadIdx.x;
    const int tx  = tid & 15;   // k-fragment (strided) / d-fragment (contiguous)
    const int ty  = tid >> 4;   // q-fragment
    const int qt  = blockIdx.x;
    const int h   = blockIdx.y;
    const int b   = blockIdx.z;
    const int q0  = qt * BQ;
    const int qrow = ty * 8;

    const size_t bh = (size_t)b * H_ + h;
    const float* Qp = Q + bh * (size_t)(L_ * D_);
    const float* Kp = K + bh * (size_t)(L_ * D_);
    const float* Vp = V + bh * (size_t)(L_ * D_);
    const float* Bp = BIAS + (size_t)b * L_ * L_;
    const int*   Mp = AM + b * L_;

    // ---- stage Q tile transposed (once per CTA) ----
    {
        const int c4 = tx * 4;
        #pragma unroll
        for (int rr = 0; rr < 8; ++rr) {
            const int q = ty + rr * 16;
            float4 v = *(const float4*)(Qp + (size_t)(q0 + q) * D_ + c4);
            QsT[(c4 + 0) * QS_STR + q] = v.x;
            QsT[(c4 + 1) * QS_STR + q] = v.y;
            QsT[(c4 + 2) * QS_STR + q] = v.z;
            QsT[(c4 + 3) * QS_STR + q] = v.w;
        }
    }

    float O[8][4];
    #pragma unroll
    for (int i = 0; i < 8; ++i)
        #pragma unroll
        for (int j = 0; j < 4; ++j) O[i][j] = 0.f;
    float mr[8], lr[8];
    #pragma unroll
    for (int i = 0; i < 8; ++i) { mr[i] = -3.0e38f; lr[i] = 0.f; }

    const float C1 = 0.125f * 1.4426950408889634f;  // (1/sqrt(64)) * log2(e)
    const float C2 = 1.4426950408889634f;           // log2(e)

    for (int kt = 0; kt < NKT; ++kt) {
        const int k0 = kt * BK;

        __syncthreads();  // previous iteration's consumers done with Vs/PsT/KsT

        // ---- stage K tile transposed + V tile natural ----
        {
            const int c4 = tx * 4;
            #pragma unroll
            for (int rr = 0; rr < 4; ++rr) {
                const int k = ty + rr * 16;
                float4 kv = *(const float4*)(Kp + (size_t)(k0 + k) * D_ + c4);
                KsT[(c4 + 0) * KS_STR + k] = kv.x;
                KsT[(c4 + 1) * KS_STR + k] = kv.y;
                KsT[(c4 + 2) * KS_STR + k] = kv.z;
                KsT[(c4 + 3) * KS_STR + k] = kv.w;
                *(float4*)(Vs + k * VS_STR + c4) =
                    *(const float4*)(Vp + (size_t)(k0 + k) * D_ + c4);
            }
        }
        __syncthreads();

        // ---- GEMM1: S[8q][4k] = Q . K^T over d ----
        float S[8][4];
        #pragma unroll
        for (int i = 0; i < 8; ++i)
            #pragma unroll
            for (int j = 0; j < 4; ++j) S[i][j] = 0.f;

        #pragma unroll 8
        for (int d = 0; d < D_; ++d) {
            float4 a0 = *(const float4*)(QsT + d * QS_STR + qrow);
            float4 a1 = *(const float4*)(QsT + d * QS_STR + qrow + 4);
            float a[8] = {a0.x, a0.y, a0.z, a0.w, a1.x, a1.y, a1.z, a1.w};
            float bb[4];
            #pragma unroll
            for (int j = 0; j < 4; ++j) bb[j] = KsT[d * KS_STR + tx + 16 * j];
            #pragma unroll
            for (int i = 0; i < 8; ++i)
                #pragma unroll
                for (int j = 0; j < 4; ++j)
                    S[i][j] = fmaf(a[i], bb[j], S[i][j]);
        }

        // ---- scale + bias + mask, into log2 domain ----
        int mv[4];
        #pragma unroll
        for (int j = 0; j < 4; ++j) mv[j] = Mp[k0 + tx + 16 * j];

        #pragma unroll
        for (int i = 0; i < 8; ++i) {
            const float* brow = Bp + (size_t)(q0 + qrow + i) * L_ + k0;
            #pragma unroll
            for (int j = 0; j < 4; ++j) {
                float bias = brow[tx + 16 * j];
                S[i][j] = mv[j] ? fmaf(S[i][j], C1, bias * C2) : -1.0e30f;
            }
        }

        // ---- online softmax (rows spread across the 16 tx lanes) ----
        #pragma unroll
        for (int i = 0; i < 8; ++i) {
            float mx = fmaxf(fmaxf(S[i][0], S[i][1]), fmaxf(S[i][2], S[i][3]));
            #pragma unroll
            for (int off = 8; off >= 1; off >>= 1)
                mx = fmaxf(mx, __shfl_xor_sync(0xffffffffu, mx, off));
            float mnew = fmaxf(mr[i], mx);
            float al = ex2f(mr[i] - mnew);
            mr[i] = mnew;
            float rs = 0.f;
            #pragma unroll
            for (int j = 0; j < 4; ++j) {
                S[i][j] = ex2f(S[i][j] - mnew);
                rs += S[i][j];
            }
            #pragma unroll
            for (int off = 8; off >= 1; off >>= 1)
                rs += __shfl_xor_sync(0xffffffffu, rs, off);
            lr[i] = lr[i] * al + rs;
            #pragma unroll
            for (int j = 0; j < 4; ++j) O[i][j] *= al;
        }

        // ---- store P^T (float4 along q, tx-spread k -> conflict-free) ----
        #pragma unroll
        for (int j = 0; j < 4; ++j) {
            const int k = tx + 16 * j;
            *(float4*)(PsT + k * PS_STR + qrow) =
                make_float4(S[0][j], S[1][j], S[2][j], S[3][j]);
            *(float4*)(PsT + k * PS_STR + qrow + 4) =
                make_float4(S[4][j], S[5][j], S[6][j], S[7][j]);
        }
        __syncthreads();

        // ---- GEMM2: O[8q][4d] += P . V over k ----
        #pragma unroll 8
        for (int k = 0; k < BK; ++k) {
            float4 a0 = *(const float4*)(PsT + k * PS_STR + qrow);
            float4 a1 = *(const float4*)(PsT + k * PS_STR + qrow + 4);
            float4 bv = *(const float4*)(Vs + k * VS_STR + tx * 4);
            float a[8] = {a0.x, a0.y, a0.z, a0.w, a1.x, a1.y, a1.z, a1.w};
            float bb[4] = {bv.x, bv.y, bv.z, bv.w};
            #pragma unroll
            for (int i = 0; i < 8; ++i)
                #pragma unroll
                for (int j = 0; j < 4; ++j)
                    O[i][j] = fmaf(a[i], bb[j], O[i][j]);
        }
    }

    // ---- epilogue: normalize and write ----
    float* outp = OUT + bh * (size_t)(L_ * D_);
    #pragma unroll
    for (int i = 0; i < 8; ++i) {
        float inv = 1.0f / lr[i];
        float4 o = make_float4(O[i][0] * inv, O[i][1] * inv,
                               O[i][2] * inv, O[i][3] * inv);
        *(float4*)(outp + (size_t)(q0 + qrow + i) * D_ + tx * 4) = o;
    }
}

extern "C" void kernel_launch(void* const* d_in, const int* in_sizes, int n_in,
                              void* d_out, int out_size)
{
    const float* Q    = (const float*)d_in[0];
    const float* K    = (const float*)d_in[1];
    const float* V    = (const float*)d_in[2];
    const int*   AM   = (const int*)d_in[3];
    const float* BIAS = (const float*)d_in[4];
    float*       OUT  = (float*)d_out;

    // Idempotent, not a stream op: safe under graph capture, deterministic.
    cudaFuncSetAttribute(SelfAttention_53369263620701_kernel,
                         cudaFuncAttributeMaxDynamicSharedMemorySize, SMEM_BYTES);

    dim3 grid(NQT, H_, B_);   // b slowest -> per-batch bias slice stays L2-resident
    dim3 block(256);
    SelfAttention_53369263620701_kernel<<<grid, block, SMEM_BYTES>>>(
        Q, K, V, AM, BIAS, OUT);
}

// round 8
// speedup vs baseline: 1.0005x; 1.0005x over previous
#include <cuda_runtime.h>
#include <cstddef>

// SelfAttention: out = softmax(Q K^T / sqrt(D) + bias, mask) @ V
// Shapes (hardcoded per reference): B=4, H=16, L=2048, D=64, all fp32.
// SIMT fp32 flash-attention baseline: 128q x 64k tiles, 8x4 register micro-tiles,
// transposed smem staging for conflict-free operand loads, log2-domain online softmax.

#define B_  4
#define H_  16
#define L_  2048
#define D_  64
#define BQ  128
#define BK  64
#define NKT (L_ / BK)   // 32
#define NQT (L_ / BQ)   // 16

// smem strides (floats). Odd 65 for scalar-store transpose (2-way max conflict);
// 132 (=33*4) keeps float4 alignment with tx-spread bank mapping.
#define QS_STR 132
#define KS_STR 65
#define VS_STR 64
#define PS_STR 132

#define OFF_QST 0
#define OFF_KST (OFF_QST + 64 * QS_STR)     // 8448
#define OFF_VS  (OFF_KST + 64 * KS_STR)     // 12608
#define OFF_PST (OFF_VS  + BK * VS_STR)     // 16704
#define SMEM_FLOATS (OFF_PST + BK * PS_STR) // 25152
#define SMEM_BYTES  (SMEM_FLOATS * 4)       // 100608

__device__ __forceinline__ float ex2f(float x) {
    float y;
    asm("ex2.approx.ftz.f32 %0, %1;" : "=f"(y) : "f"(x));
    return y;
}

extern __shared__ float sm_dyn[];

__global__ __launch_bounds__(256, 2)
void SelfAttention_53369263620701_kernel(
    const float* __restrict__ Q, const float* __restrict__ K,
    const float* __restrict__ V, const int* __restrict__ AM,
    const float* __restrict__ BIAS, float* __restrict__ OUT)
{
    float* QsT = sm_dyn + OFF_QST;  // [d][q]   d:64, q:128 (stride 132)
    float* KsT = sm_dyn + OFF_KST;  // [d][k]   d:64, k:64  (stride 65)
    float* Vs  = sm_dyn + OFF_VS;   // [k][d]   k:64, d:64  (stride 64)
    float* PsT = sm_dyn + OFF_PST;  // [k][q]   k:64, q:128 (stride 132)

    const int tid = threadIdx.x;
    const int tx  = tid & 15;   // k-fragment (strided) / d-fragment (contiguous)
    const int ty  = tid >> 4;   // q-fragment
    const int qt  = blockIdx.x;
    const int h   = blockIdx.y;
    const int b   = blockIdx.z;
    const int q0  = qt * BQ;
    const int qrow = ty * 8;

    const size_t bh = (size_t)b * H_ + h;
    const float* Qp = Q + bh * (size_t)(L_ * D_);
    const float* Kp = K + bh * (size_t)(L_ * D_);
    const float* Vp = V + bh * (size_t)(L_ * D_);
    const float* Bp = BIAS + (size_t)b * L_ * L_;
    const int*   Mp = AM + b * L_;

    // ---- stage Q tile transposed (once per CTA) ----
    {
        const int c4 = tx * 4;
        #pragma unroll
        for (int rr = 0; rr < 8; ++rr) {
            const int q = ty + rr * 16;
            float4 v = *(const float4*)(Qp + (size_t)(q0 + q) * D_ + c4);
            QsT[(c4 + 0) * QS_STR + q] = v.x;
            QsT[(c4 + 1) * QS_STR + q] = v.y;
            QsT[(c4 + 2) * QS_STR + q] = v.z;
            QsT[(c4 + 3) * QS_STR + q] = v.w;
        }
    }

    float O[8][4];
    #pragma unroll
    for (int i = 0; i < 8; ++i)
        #pragma unroll
        for (int j = 0; j < 4; ++j) O[i][j] = 0.f;
    float mr[8], lr[8];
    #pragma unroll
    for (int i = 0; i < 8; ++i) { mr[i] = -3.0e38f; lr[i] = 0.f; }

    const float C1 = 0.125f * 1.4426950408889634f;  // (1/sqrt(64)) * log2(e)
    const float C2 = 1.4426950408889634f;           // log2(e)

    for (int kt = 0; kt < NKT; ++kt) {
        const int k0 = kt * BK;

        __syncthreads();  // previous iteration's consumers done with Vs/PsT/KsT

        // ---- stage K tile transposed + V tile natural ----
        {
            const int c4 = tx * 4;
            #pragma unroll
            for (int rr = 0; rr < 4; ++rr) {
                const int k = ty + rr * 16;
                float4 kv = *(const float4*)(Kp + (size_t)(k0 + k) * D_ + c4);
                KsT[(c4 + 0) * KS_STR + k] = kv.x;
                KsT[(c4 + 1) * KS_STR + k] = kv.y;
                KsT[(c4 + 2) * KS_STR + k] = kv.z;
                KsT[(c4 + 3) * KS_STR + k] = kv.w;
                *(float4*)(Vs + k * VS_STR + c4) =
                    *(const float4*)(Vp + (size_t)(k0 + k) * D_ + c4);
            }
        }
        __syncthreads();

        // ---- GEMM1: S[8q][4k] = Q . K^T over d ----
        float S[8][4];
        #pragma unroll
        for (int i = 0; i < 8; ++i)
            #pragma unroll
            for (int j = 0; j < 4; ++j) S[i][j] = 0.f;

        #pragma unroll 8
        for (int d = 0; d < D_; ++d) {
            float4 a0 = *(const float4*)(QsT + d * QS_STR + qrow);
            float4 a1 = *(const float4*)(QsT + d * QS_STR + qrow + 4);
            float a[8] = {a0.x, a0.y, a0.z, a0.w, a1.x, a1.y, a1.z, a1.w};
            float bb[4];
            #pragma unroll
            for (int j = 0; j < 4; ++j) bb[j] = KsT[d * KS_STR + tx + 16 * j];
            #pragma unroll
            for (int i = 0; i < 8; ++i)
                #pragma unroll
                for (int j = 0; j < 4; ++j)
                    S[i][j] = fmaf(a[i], bb[j], S[i][j]);
        }

        // ---- scale + bias + mask, into log2 domain ----
        int mv[4];
        #pragma unroll
        for (int j = 0; j < 4; ++j) mv[j] = Mp[k0 + tx + 16 * j];

        #pragma unroll
        for (int i = 0; i < 8; ++i) {
            const float* brow = Bp + (size_t)(q0 + qrow + i) * L_ + k0;
            #pragma unroll
            for (int j = 0; j < 4; ++j) {
                float bias = brow[tx + 16 * j];
                S[i][j] = mv[j] ? fmaf(S[i][j], C1, bias * C2) : -1.0e30f;
            }
        }

        // ---- online softmax (rows spread across the 16 tx lanes) ----
        #pragma unroll
        for (int i = 0; i < 8; ++i) {
            float mx = fmaxf(fmaxf(S[i][0], S[i][1]), fmaxf(S[i][2], S[i][3]));
            #pragma unroll
            for (int off = 8; off >= 1; off >>= 1)
                mx = fmaxf(mx, __shfl_xor_sync(0xffffffffu, mx, off));
            float mnew = fmaxf(mr[i], mx);
            float al = ex2f(mr[i] - mnew);
            mr[i] = mnew;
            float rs = 0.f;
            #pragma unroll
            for (int j = 0; j < 4; ++j) {
                S[i][j] = ex2f(S[i][j] - mnew);
                rs += S[i][j];
            }
            #pragma unroll
            for (int off = 8; off >= 1; off >>= 1)
                rs += __shfl_xor_sync(0xffffffffu, rs, off);
            lr[i] = lr[i] * al + rs;
            #pragma unroll
            for (int j = 0; j < 4; ++j) O[i][j] *= al;
        }

        // ---- store P^T (float4 along q, tx-spread k -> conflict-free) ----
        #pragma unroll
        for (int j = 0; j < 4; ++j) {
            const int k = tx + 16 * j;
            *(float4*)(PsT + k * PS_STR + qrow) =
                make_float4(S[0][j], S[1][j], S[2][j], S[3][j]);
            *(float4*)(PsT + k * PS_STR + qrow + 4) =
                make_float4(S[4][j], S[5][j], S[6][j], S[7][j]);
        }
        __syncthreads();

        // ---- GEMM2: O[8q][4d] += P . V over k ----
        #pragma unroll 8
        for (int k = 0; k < BK; ++k) {
            float4 a0 = *(const float4*)(PsT + k * PS_STR + qrow);
            float4 a1 = *(const float4*)(PsT + k * PS_STR + qrow + 4);
            float4 bv = *(const float4*)(Vs + k * VS_STR + tx * 4);
            float a[8] = {a0.x, a0.y, a0.z, a0.w, a1.x, a1.y, a1.z, a1.w};
            float bb[4] = {bv.x, bv.y, bv.z, bv.w};
            #pragma unroll
            for (int i = 0; i < 8; ++i)
                #pragma unroll
                for (int j = 0; j < 4; ++j)
                    O[i][j] = fmaf(a[i], bb[j], O[i][j]);
        }
    }

    // ---- epilogue: normalize and write ----
    float* outp = OUT + bh * (size_t)(L_ * D_);
    #pragma unroll
    for (int i = 0; i < 8; ++i) {
        float inv = 1.0f / lr[i];
        float4 o = make_float4(O[i][0] * inv, O[i][1] * inv,
                               O[i][2] * inv, O[i][3] * inv);
        *(float4*)(outp + (size_t)(q0 + qrow + i) * D_ + tx * 4) = o;
    }
}

extern "C" void kernel_launch(void* const* d_in, const int* in_sizes, int n_in,
                              void* d_out, int out_size)
{
    const float* Q    = (const float*)d_in[0];
    const float* K    = (const float*)d_in[1];
    const float* V    = (const float*)d_in[2];
    const int*   AM   = (const int*)d_in[3];
    const float* BIAS = (const float*)d_in[4];
    float*       OUT  = (float*)d_out;

    // Idempotent, not a stream op: safe under graph capture, deterministic.
    cudaFuncSetAttribute(SelfAttention_53369263620701_kernel,
                         cudaFuncAttributeMaxDynamicSharedMemorySize, SMEM_BYTES);

    dim3 grid(NQT, H_, B_);   // b slowest -> per-batch bias slice stays L2-resident
    dim3 block(256);
    SelfAttention_53369263620701_kernel<<<grid, block, SMEM_BYTES>>>(
        Q, K, V, AM, BIAS, OUT);
}

// round 9
// speedup vs baseline: 1.0009x; 1.0004x over previous
#include <cuda_runtime.h>
#include <cstddef>

// SelfAttention: out = softmax(Q K^T / sqrt(D) + bias, mask) @ V
// Shapes (hardcoded per reference): B=4, H=16, L=2048, D=64, all fp32.
// SIMT fp32 flash-attention baseline: 128q x 64k tiles, 8x4 register micro-tiles,
// transposed smem staging for conflict-free operand loads, log2-domain online softmax.

#define B_  4
#define H_  16
#define L_  2048
#define D_  64
#define BQ  128
#define BK  64
#define NKT (L_ / BK)   // 32
#define NQT (L_ / BQ)   // 16

// smem strides (floats). Odd 65 for scalar-store transpose (2-way max conflict);
// 132 (=33*4) keeps float4 alignment with tx-spread bank mapping.
#define QS_STR 132
#define KS_STR 65
#define VS_STR 64
#define PS_STR 132

#define OFF_QST 0
#define OFF_KST (OFF_QST + 64 * QS_STR)     // 8448
#define OFF_VS  (OFF_KST + 64 * KS_STR)     // 12608
#define OFF_PST (OFF_VS  + BK * VS_STR)     // 16704
#define SMEM_FLOATS (OFF_PST + BK * PS_STR) // 25152
#define SMEM_BYTES  (SMEM_FLOATS * 4)       // 100608

__device__ __forceinline__ float ex2f(float x) {
    float y;
    asm("ex2.approx.ftz.f32 %0, %1;" : "=f"(y) : "f"(x));
    return y;
}

extern __shared__ float sm_dyn[];

__global__ __launch_bounds__(256, 2)
void SelfAttention_53369263620701_kernel(
    const float* __restrict__ Q, const float* __restrict__ K,
    const float* __restrict__ V, const int* __restrict__ AM,
    const float* __restrict__ BIAS, float* __restrict__ OUT)
{
    float* QsT = sm_dyn + OFF_QST;  // [d][q]   d:64, q:128 (stride 132)
    float* KsT = sm_dyn + OFF_KST;  // [d][k]   d:64, k:64  (stride 65)
    float* Vs  = sm_dyn + OFF_VS;   // [k][d]   k:64, d:64  (stride 64)
    float* PsT = sm_dyn + OFF_PST;  // [k][q]   k:64, q:128 (stride 132)

    const int tid = threadIdx.x;
    const int tx  = tid & 15;   // k-fragment (strided) / d-fragment (contiguous)
    const int ty  = tid >> 4;   // q-fragment
    const int qt  = blockIdx.x;
    const int h   = blockIdx.y;
    const int b   = blockIdx.z;
    const int q0  = qt * BQ;
    const int qrow = ty * 8;

    const size_t bh = (size_t)b * H_ + h;
    const float* Qp = Q + bh * (size_t)(L_ * D_);
    const float* Kp = K + bh * (size_t)(L_ * D_);
    const float* Vp = V + bh * (size_t)(L_ * D_);
    const float* Bp = BIAS + (size_t)b * L_ * L_;
    const int*   Mp = AM + b * L_;

    // ---- stage Q tile transposed (once per CTA) ----
    {
        const int c4 = tx * 4;
        #pragma unroll
        for (int rr = 0; rr < 8; ++rr) {
            const int q = ty + rr * 16;
            float4 v = *(const float4*)(Qp + (size_t)(q0 + q) * D_ + c4);
            QsT[(c4 + 0) * QS_STR + q] = v.x;
            QsT[(c4 + 1) * QS_STR + q] = v.y;
            QsT[(c4 + 2) * QS_STR + q] = v.z;
            QsT[(c4 + 3) * QS_STR + q] = v.w;
        }
    }

    float O[8][4];
    #pragma unroll
    for (int i = 0; i < 8; ++i)
        #pragma unroll
        for (int j = 0; j < 4; ++j) O[i][j] = 0.f;
    float mr[8], lr[8];
    #pragma unroll
    for (int i = 0; i < 8; ++i) { mr[i] = -3.0e38f; lr[i] = 0.f; }

    const float C1 = 0.125f * 1.4426950408889634f;  // (1/sqrt(64)) * log2(e)
    const float C2 = 1.4426950408889634f;           // log2(e)

    for (int kt = 0; kt < NKT; ++kt) {
        const int k0 = kt * BK;

        __syncthreads();  // previous iteration's consumers done with Vs/PsT/KsT

        // ---- stage K tile transposed + V tile natural ----
        {
            const int c4 = tx * 4;
            #pragma unroll
            for (int rr = 0; rr < 4; ++rr) {
                const int k = ty + rr * 16;
                float4 kv = *(const float4*)(Kp + (size_t)(k0 + k) * D_ + c4);
                KsT[(c4 + 0) * KS_STR + k] = kv.x;
                KsT[(c4 + 1) * KS_STR + k] = kv.y;
                KsT[(c4 + 2) * KS_STR + k] = kv.z;
                KsT[(c4 + 3) * KS_STR + k] = kv.w;
                *(float4*)(Vs + k * VS_STR + c4) =
                    *(const float4*)(Vp + (size_t)(k0 + k) * D_ + c4);
            }
        }
        __syncthreads();

        // ---- GEMM1: S[8q][4k] = Q . K^T over d ----
        float S[8][4];
        #pragma unroll
        for (int i = 0; i < 8; ++i)
            #pragma unroll
            for (int j = 0; j < 4; ++j) S[i][j] = 0.f;

        #pragma unroll 8
        for (int d = 0; d < D_; ++d) {
            float4 a0 = *(const float4*)(QsT + d * QS_STR + qrow);
            float4 a1 = *(const float4*)(QsT + d * QS_STR + qrow + 4);
            float a[8] = {a0.x, a0.y, a0.z, a0.w, a1.x, a1.y, a1.z, a1.w};
            float bb[4];
            #pragma unroll
            for (int j = 0; j < 4; ++j) bb[j] = KsT[d * KS_STR + tx + 16 * j];
            #pragma unroll
            for (int i = 0; i < 8; ++i)
                #pragma unroll
                for (int j = 0; j < 4; ++j)
                    S[i][j] = fmaf(a[i], bb[j], S[i][j]);
        }

        // ---- scale + bias + mask, into log2 domain ----
        int mv[4];
        #pragma unroll
        for (int j = 0; j < 4; ++j) mv[j] = Mp[k0 + tx + 16 * j];

        #pragma unroll
        for (int i = 0; i < 8; ++i) {
            const float* brow = Bp + (size_t)(q0 + qrow + i) * L_ + k0;
            #pragma unroll
            for (int j = 0; j < 4; ++j) {
                float bias = brow[tx + 16 * j];
                S[i][j] = mv[j] ? fmaf(S[i][j], C1, bias * C2) : -1.0e30f;
            }
        }

        // ---- online softmax (rows spread across the 16 tx lanes) ----
        #pragma unroll
        for (int i = 0; i < 8; ++i) {
            float mx = fmaxf(fmaxf(S[i][0], S[i][1]), fmaxf(S[i][2], S[i][3]));
            #pragma unroll
            for (int off = 8; off >= 1; off >>= 1)
                mx = fmaxf(mx, __shfl_xor_sync(0xffffffffu, mx, off));
            float mnew = fmaxf(mr[i], mx);
            float al = ex2f(mr[i] - mnew);
            mr[i] = mnew;
            float rs = 0.f;
            #pragma unroll
            for (int j = 0; j < 4; ++j) {
                S[i][j] = ex2f(S[i][j] - mnew);
                rs += S[i][j];
            }
            #pragma unroll
            for (int off = 8; off >= 1; off >>= 1)
                rs += __shfl_xor_sync(0xffffffffu, rs, off);
            lr[i] = lr[i] * al + rs;
            #pragma unroll
            for (int j = 0; j < 4; ++j) O[i][j] *= al;
        }

        // ---- store P^T (float4 along q, tx-spread k -> conflict-free) ----
        #pragma unroll
        for (int j = 0; j < 4; ++j) {
            const int k = tx + 16 * j;
            *(float4*)(PsT + k * PS_STR + qrow) =
                make_float4(S[0][j], S[1][j], S[2][j], S[3][j]);
            *(float4*)(PsT + k * PS_STR + qrow + 4) =
                make_float4(S[4][j], S[5][j], S[6][j], S[7][j]);
        }
        __syncthreads();

        // ---- GEMM2: O[8q][4d] += P . V over k ----
        #pragma unroll 8
        for (int k = 0; k < BK; ++k) {
            float4 a0 = *(const float4*)(PsT + k * PS_STR + qrow);
            float4 a1 = *(const float4*)(PsT + k * PS_STR + qrow + 4);
            float4 bv = *(const float4*)(Vs + k * VS_STR + tx * 4);
            float a[8] = {a0.x, a0.y, a0.z, a0.w, a1.x, a1.y, a1.z, a1.w};
            float bb[4] = {bv.x, bv.y, bv.z, bv.w};
            #pragma unroll
            for (int i = 0; i < 8; ++i)
                #pragma unroll
                for (int j = 0; j < 4; ++j)
                    O[i][j] = fmaf(a[i], bb[j], O[i][j]);
        }
    }

    // ---- epilogue: normalize and write ----
    float* outp = OUT + bh * (size_t)(L_ * D_);
    #pragma unroll
    for (int i = 0; i < 8; ++i) {
        float inv = 1.0f / lr[i];
        float4 o = make_float4(O[i][0] * inv, O[i][1] * inv,
                               O[i][2] * inv, O[i][3] * inv);
        *(float4*)(outp + (size_t)(q0 + qrow + i) * D_ + tx * 4) = o;
    }
}

extern "C" void kernel_launch(void* const* d_in, const int* in_sizes, int n_in,
                              void* d_out, int out_size)
{
    const float* Q    = (const float*)d_in[0];
    const float* K    = (const float*)d_in[1];
    const float* V    = (const float*)d_in[2];
    const int*   AM   = (const int*)d_in[3];
    const float* BIAS = (const float*)d_in[4];
    float*       OUT  = (float*)d_out;

    // Idempotent, not a stream op: safe under graph capture, deterministic.
    cudaFuncSetAttribute(SelfAttention_53369263620701_kernel,
                         cudaFuncAttributeMaxDynamicSharedMemorySize, SMEM_BYTES);

    dim3 grid(NQT, H_, B_);   // b slowest -> per-batch bias slice stays L2-resident
    dim3 block(256);
    SelfAttention_53369263620701_kernel<<<grid, block, SMEM_BYTES>>>(
        Q, K, V, AM, BIAS, OUT);
}

// round 10
// speedup vs baseline: 1.0011x; 1.0002x over previous
#include <cuda_runtime.h>
#include <cstddef>

// SelfAttention: out = softmax(Q K^T / sqrt(D) + bias, mask) @ V
// Shapes (hardcoded per reference): B=4, H=16, L=2048, D=64, all fp32.
// SIMT fp32 flash-attention baseline: 128q x 64k tiles, 8x4 register micro-tiles,
// transposed smem staging for conflict-free operand loads, log2-domain online softmax.

#define B_  4
#define H_  16
#define L_  2048
#define D_  64
#define BQ  128
#define BK  64
#define NKT (L_ / BK)   // 32
#define NQT (L_ / BQ)   // 16

// smem strides (floats). Odd 65 for scalar-store transpose (2-way max conflict);
// 132 (=33*4) keeps float4 alignment with tx-spread bank mapping.
#define QS_STR 132
#define KS_STR 65
#define VS_STR 64
#define PS_STR 132

#define OFF_QST 0
#define OFF_KST (OFF_QST + 64 * QS_STR)     // 8448
#define OFF_VS  (OFF_KST + 64 * KS_STR)     // 12608
#define OFF_PST (OFF_VS  + BK * VS_STR)     // 16704
#define SMEM_FLOATS (OFF_PST + BK * PS_STR) // 25152
#define SMEM_BYTES  (SMEM_FLOATS * 4)       // 100608

__device__ __forceinline__ float ex2f(float x) {
    float y;
    asm("ex2.approx.ftz.f32 %0, %1;" : "=f"(y) : "f"(x));
    return y;
}

extern __shared__ float sm_dyn[];

__global__ __launch_bounds__(256, 2)
void SelfAttention_53369263620701_kernel(
    const float* __restrict__ Q, const float* __restrict__ K,
    const float* __restrict__ V, const int* __restrict__ AM,
    const float* __restrict__ BIAS, float* __restrict__ OUT)
{
    float* QsT = sm_dyn + OFF_QST;  // [d][q]   d:64, q:128 (stride 132)
    float* KsT = sm_dyn + OFF_KST;  // [d][k]   d:64, k:64  (stride 65)
    float* Vs  = sm_dyn + OFF_VS;   // [k][d]   k:64, d:64  (stride 64)
    float* PsT = sm_dyn + OFF_PST;  // [k][q]   k:64, q:128 (stride 132)

    const int tid = threadIdx.x;
    const int tx  = tid & 15;   // k-fragment (strided) / d-fragment (contiguous)
    const int ty  = tid >> 4;   // q-fragment
    const int qt  = blockIdx.x;
    const int h   = blockIdx.y;
    const int b   = blockIdx.z;
    const int q0  = qt * BQ;
    const int qrow = ty * 8;

    const size_t bh = (size_t)b * H_ + h;
    const float* Qp = Q + bh * (size_t)(L_ * D_);
    const float* Kp = K + bh * (size_t)(L_ * D_);
    const float* Vp = V + bh * (size_t)(L_ * D_);
    const float* Bp = BIAS + (size_t)b * L_ * L_;
    const int*   Mp = AM + b * L_;

    // ---- stage Q tile transposed (once per CTA) ----
    {
        const int c4 = tx * 4;
        #pragma unroll
        for (int rr = 0; rr < 8; ++rr) {
            const int q = ty + rr * 16;
            float4 v = *(const float4*)(Qp + (size_t)(q0 + q) * D_ + c4);
            QsT[(c4 + 0) * QS_STR + q] = v.x;
            QsT[(c4 + 1) * QS_STR + q] = v.y;
            QsT[(c4 + 2) * QS_STR + q] = v.z;
            QsT[(c4 + 3) * QS_STR + q] = v.w;
        }
    }

    float O[8][4];
    #pragma unroll
    for (int i = 0; i < 8; ++i)
        #pragma unroll
        for (int j = 0; j < 4; ++j) O[i][j] = 0.f;
    float mr[8], lr[8];
    #pragma unroll
    for (int i = 0; i < 8; ++i) { mr[i] = -3.0e38f; lr[i] = 0.f; }

    const float C1 = 0.125f * 1.4426950408889634f;  // (1/sqrt(64)) * log2(e)
    const float C2 = 1.4426950408889634f;           // log2(e)

    for (int kt = 0; kt < NKT; ++kt) {
        const int k0 = kt * BK;

        __syncthreads();  // previous iteration's consumers done with Vs/PsT/KsT

        // ---- stage K tile transposed + V tile natural ----
        {
            const int c4 = tx * 4;
            #pragma unroll
            for (int rr = 0; rr < 4; ++rr) {
                const int k = ty + rr * 16;
                float4 kv = *(const float4*)(Kp + (size_t)(k0 + k) * D_ + c4);
                KsT[(c4 + 0) * KS_STR + k] = kv.x;
                KsT[(c4 + 1) * KS_STR + k] = kv.y;
                KsT[(c4 + 2) * KS_STR + k] = kv.z;
                KsT[(c4 + 3) * KS_STR + k] = kv.w;
                *(float4*)(Vs + k * VS_STR + c4) =
                    *(const float4*)(Vp + (size_t)(k0 + k) * D_ + c4);
            }
        }
        __syncthreads();

        // ---- GEMM1: S[8q][4k] = Q . K^T over d ----
        float S[8][4];
        #pragma unroll
        for (int i = 0; i < 8; ++i)
            #pragma unroll
            for (int j = 0; j < 4; ++j) S[i][j] = 0.f;

        #pragma unroll 8
        for (int d = 0; d < D_; ++d) {
            float4 a0 = *(const float4*)(QsT + d * QS_STR + qrow);
            float4 a1 = *(const float4*)(QsT + d * QS_STR + qrow + 4);
            float a[8] = {a0.x, a0.y, a0.z, a0.w, a1.x, a1.y, a1.z, a1.w};
            float bb[4];
            #pragma unroll
            for (int j = 0; j < 4; ++j) bb[j] = KsT[d * KS_STR + tx + 16 * j];
            #pragma unroll
            for (int i = 0; i < 8; ++i)
                #pragma unroll
                for (int j = 0; j < 4; ++j)
                    S[i][j] = fmaf(a[i], bb[j], S[i][j]);
        }

        // ---- scale + bias + mask, into log2 domain ----
        int mv[4];
        #pragma unroll
        for (int j = 0; j < 4; ++j) mv[j] = Mp[k0 + tx + 16 * j];

        #pragma unroll
        for (int i = 0; i < 8; ++i) {
            const float* brow = Bp + (size_t)(q0 + qrow + i) * L_ + k0;
            #pragma unroll
            for (int j = 0; j < 4; ++j) {
                float bias = brow[tx + 16 * j];
                S[i][j] = mv[j] ? fmaf(S[i][j], C1, bias * C2) : -1.0e30f;
            }
        }

        // ---- online softmax (rows spread across the 16 tx lanes) ----
        #pragma unroll
        for (int i = 0; i < 8; ++i) {
            float mx = fmaxf(fmaxf(S[i][0], S[i][1]), fmaxf(S[i][2], S[i][3]));
            #pragma unroll
            for (int off = 8; off >= 1; off >>= 1)
                mx = fmaxf(mx, __shfl_xor_sync(0xffffffffu, mx, off));
            float mnew = fmaxf(mr[i], mx);
            float al = ex2f(mr[i] - mnew);
            mr[i] = mnew;
            float rs = 0.f;
            #pragma unroll
            for (int j = 0; j < 4; ++j) {
                S[i][j] = ex2f(S[i][j] - mnew);
                rs += S[i][j];
            }
            #pragma unroll
            for (int off = 8; off >= 1; off >>= 1)
                rs += __shfl_xor_sync(0xffffffffu, rs, off);
            lr[i] = lr[i] * al + rs;
            #pragma unroll
            for (int j = 0; j < 4; ++j) O[i][j] *= al;
        }

        // ---- store P^T (float4 along q, tx-spread k -> conflict-free) ----
        #pragma unroll
        for (int j = 0; j < 4; ++j) {
            const int k = tx + 16 * j;
            *(float4*)(PsT + k * PS_STR + qrow) =
                make_float4(S[0][j], S[1][j], S[2][j], S[3][j]);
            *(float4*)(PsT + k * PS_STR + qrow + 4) =
                make_float4(S[4][j], S[5][j], S[6][j], S[7][j]);
        }
        __syncthreads();

        // ---- GEMM2: O[8q][4d] += P . V over k ----
        #pragma unroll 8
        for (int k = 0; k < BK; ++k) {
            float4 a0 = *(const float4*)(PsT + k * PS_STR + qrow);
            float4 a1 = *(const float4*)(PsT + k * PS_STR + qrow + 4);
            float4 bv = *(const float4*)(Vs + k * VS_STR + tx * 4);
            float a[8] = {a0.x, a0.y, a0.z, a0.w, a1.x, a1.y, a1.z, a1.w};
            float bb[4] = {bv.x, bv.y, bv.z, bv.w};
            #pragma unroll
            for (int i = 0; i < 8; ++i)
                #pragma unroll
                for (int j = 0; j < 4; ++j)
                    O[i][j] = fmaf(a[i], bb[j], O[i][j]);
        }
    }

    // ---- epilogue: normalize and write ----
    float* outp = OUT + bh * (size_t)(L_ * D_);
    #pragma unroll
    for (int i = 0; i < 8; ++i) {
        float inv = 1.0f / lr[i];
        float4 o = make_float4(O[i][0] * inv, O[i][1] * inv,
                               O[i][2] * inv, O[i][3] * inv);
        *(float4*)(outp + (size_t)(q0 + qrow + i) * D_ + tx * 4) = o;
    }
}

extern "C" void kernel_launch(void* const* d_in, const int* in_sizes, int n_in,
                              void* d_out, int out_size)
{
    const float* Q    = (const float*)d_in[0];
    const float* K    = (const float*)d_in[1];
    const float* V    = (const float*)d_in[2];
    const int*   AM   = (const int*)d_in[3];
    const float* BIAS = (const float*)d_in[4];
    float*       OUT  = (float*)d_out;

    // Idempotent, not a stream op: safe under graph capture, deterministic.
    cudaFuncSetAttribute(SelfAttention_53369263620701_kernel,
                         cudaFuncAttributeMaxDynamicSharedMemorySize, SMEM_BYTES);

    dim3 grid(NQT, H_, B_);   // b slowest -> per-batch bias slice stays L2-resident
    dim3 block(256);
    SelfAttention_53369263620701_kernel<<<grid, block, SMEM_BYTES>>>(
        Q, K, V, AM, BIAS, OUT);
}

// round 11
// speedup vs baseline: 1.0017x; 1.0006x over previous
#include <cuda_runtime.h>
#include <cstddef>

// SelfAttention: out = softmax(Q K^T / sqrt(D) + bias, mask) @ V
// Shapes (hardcoded per reference): B=4, H=16, L=2048, D=64, all fp32.
// SIMT fp32 flash-attention baseline: 128q x 64k tiles, 8x4 register micro-tiles,
// transposed smem staging for conflict-free operand loads, log2-domain online softmax.

#define B_  4
#define H_  16
#define L_  2048
#define D_  64
#define BQ  128
#define BK  64
#define NKT (L_ / BK)   // 32
#define NQT (L_ / BQ)   // 16

// smem strides (floats). Odd 65 for scalar-store transpose (2-way max conflict);
// 132 (=33*4) keeps float4 alignment with tx-spread bank mapping.
#define QS_STR 132
#define KS_STR 65
#define VS_STR 64
#define PS_STR 132

#define OFF_QST 0
#define OFF_KST (OFF_QST + 64 * QS_STR)     // 8448
#define OFF_VS  (OFF_KST + 64 * KS_STR)     // 12608
#define OFF_PST (OFF_VS  + BK * VS_STR)     // 16704
#define SMEM_FLOATS (OFF_PST + BK * PS_STR) // 25152
#define SMEM_BYTES  (SMEM_FLOATS * 4)       // 100608

__device__ __forceinline__ float ex2f(float x) {
    float y;
    asm("ex2.approx.ftz.f32 %0, %1;" : "=f"(y) : "f"(x));
    return y;
}

extern __shared__ float sm_dyn[];

__global__ __launch_bounds__(256, 2)
void SelfAttention_53369263620701_kernel(
    const float* __restrict__ Q, const float* __restrict__ K,
    const float* __restrict__ V, const int* __restrict__ AM,
    const float* __restrict__ BIAS, float* __restrict__ OUT)
{
    float* QsT = sm_dyn + OFF_QST;  // [d][q]   d:64, q:128 (stride 132)
    float* KsT = sm_dyn + OFF_KST;  // [d][k]   d:64, k:64  (stride 65)
    float* Vs  = sm_dyn + OFF_VS;   // [k][d]   k:64, d:64  (stride 64)
    float* PsT = sm_dyn + OFF_PST;  // [k][q]   k:64, q:128 (stride 132)

    const int tid = threadIdx.x;
    const int tx  = tid & 15;   // k-fragment (strided) / d-fragment (contiguous)
    const int ty  = tid >> 4;   // q-fragment
    const int qt  = blockIdx.x;
    const int h   = blockIdx.y;
    const int b   = blockIdx.z;
    const int q0  = qt * BQ;
    const int qrow = ty * 8;

    const size_t bh = (size_t)b * H_ + h;
    const float* Qp = Q + bh * (size_t)(L_ * D_);
    const float* Kp = K + bh * (size_t)(L_ * D_);
    const float* Vp = V + bh * (size_t)(L_ * D_);
    const float* Bp = BIAS + (size_t)b * L_ * L_;
    const int*   Mp = AM + b * L_;

    // ---- stage Q tile transposed (once per CTA) ----
    {
        const int c4 = tx * 4;
        #pragma unroll
        for (int rr = 0; rr < 8; ++rr) {
            const int q = ty + rr * 16;
            float4 v = *(const float4*)(Qp + (size_t)(q0 + q) * D_ + c4);
            QsT[(c4 + 0) * QS_STR + q] = v.x;
            QsT[(c4 + 1) * QS_STR + q] = v.y;
            QsT[(c4 + 2) * QS_STR + q] = v.z;
            QsT[(c4 + 3) * QS_STR + q] = v.w;
        }
    }

    float O[8][4];
    #pragma unroll
    for (int i = 0; i < 8; ++i)
        #pragma unroll
        for (int j = 0; j < 4; ++j) O[i][j] = 0.f;
    float mr[8], lr[8];
    #pragma unroll
    for (int i = 0; i < 8; ++i) { mr[i] = -3.0e38f; lr[i] = 0.f; }

    const float C1 = 0.125f * 1.4426950408889634f;  // (1/sqrt(64)) * log2(e)
    const float C2 = 1.4426950408889634f;           // log2(e)

    for (int kt = 0; kt < NKT; ++kt) {
        const int k0 = kt * BK;

        __syncthreads();  // previous iteration's consumers done with Vs/PsT/KsT

        // ---- stage K tile transposed + V tile natural ----
        {
            const int c4 = tx * 4;
            #pragma unroll
            for (int rr = 0; rr < 4; ++rr) {
                const int k = ty + rr * 16;
                float4 kv = *(const float4*)(Kp + (size_t)(k0 + k) * D_ + c4);
                KsT[(c4 + 0) * KS_STR + k] = kv.x;
                KsT[(c4 + 1) * KS_STR + k] = kv.y;
                KsT[(c4 + 2) * KS_STR + k] = kv.z;
                KsT[(c4 + 3) * KS_STR + k] = kv.w;
                *(float4*)(Vs + k * VS_STR + c4) =
                    *(const float4*)(Vp + (size_t)(k0 + k) * D_ + c4);
            }
        }
        __syncthreads();

        // ---- GEMM1: S[8q][4k] = Q . K^T over d ----
        float S[8][4];
        #pragma unroll
        for (int i = 0; i < 8; ++i)
            #pragma unroll
            for (int j = 0; j < 4; ++j) S[i][j] = 0.f;

        #pragma unroll 8
        for (int d = 0; d < D_; ++d) {
            float4 a0 = *(const float4*)(QsT + d * QS_STR + qrow);
            float4 a1 = *(const float4*)(QsT + d * QS_STR + qrow + 4);
            float a[8] = {a0.x, a0.y, a0.z, a0.w, a1.x, a1.y, a1.z, a1.w};
            float bb[4];
            #pragma unroll
            for (int j = 0; j < 4; ++j) bb[j] = KsT[d * KS_STR + tx + 16 * j];
            #pragma unroll
            for (int i = 0; i < 8; ++i)
                #pragma unroll
                for (int j = 0; j < 4; ++j)
                    S[i][j] = fmaf(a[i], bb[j], S[i][j]);
        }

        // ---- scale + bias + mask, into log2 domain ----
        int mv[4];
        #pragma unroll
        for (int j = 0; j < 4; ++j) mv[j] = Mp[k0 + tx + 16 * j];

        #pragma unroll
        for (int i = 0; i < 8; ++i) {
            const float* brow = Bp + (size_t)(q0 + qrow + i) * L_ + k0;
            #pragma unroll
            for (int j = 0; j < 4; ++j) {
                float bias = brow[tx + 16 * j];
                S[i][j] = mv[j] ? fmaf(S[i][j], C1, bias * C2) : -1.0e30f;
            }
        }

        // ---- online softmax (rows spread across the 16 tx lanes) ----
        #pragma unroll
        for (int i = 0; i < 8; ++i) {
            float mx = fmaxf(fmaxf(S[i][0], S[i][1]), fmaxf(S[i][2], S[i][3]));
            #pragma unroll
            for (int off = 8; off >= 1; off >>= 1)
                mx = fmaxf(mx, __shfl_xor_sync(0xffffffffu, mx, off));
            float mnew = fmaxf(mr[i], mx);
            float al = ex2f(mr[i] - mnew);
            mr[i] = mnew;
            float rs = 0.f;
            #pragma unroll
            for (int j = 0; j < 4; ++j) {
                S[i][j] = ex2f(S[i][j] - mnew);
                rs += S[i][j];
            }
            #pragma unroll
            for (int off = 8; off >= 1; off >>= 1)
                rs += __shfl_xor_sync(0xffffffffu, rs, off);
            lr[i] = lr[i] * al + rs;
            #pragma unroll
            for (int j = 0; j < 4; ++j) O[i][j] *= al;
        }

        // ---- store P^T (float4 along q, tx-spread k -> conflict-free) ----
        #pragma unroll
        for (int j = 0; j < 4; ++j) {
            const int k = tx + 16 * j;
            *(float4*)(PsT + k * PS_STR + qrow) =
                make_float4(S[0][j], S[1][j], S[2][j], S[3][j]);
            *(float4*)(PsT + k * PS_STR + qrow + 4) =
                make_float4(S[4][j], S[5][j], S[6][j], S[7][j]);
        }
        __syncthreads();

        // ---- GEMM2: O[8q][4d] += P . V over k ----
        #pragma unroll 8
        for (int k = 0; k < BK; ++k) {
            float4 a0 = *(const float4*)(PsT + k * PS_STR + qrow);
            float4 a1 = *(const float4*)(PsT + k * PS_STR + qrow + 4);
            float4 bv = *(const float4*)(Vs + k * VS_STR + tx * 4);
            float a[8] = {a0.x, a0.y, a0.z, a0.w, a1.x, a1.y, a1.z, a1.w};
            float bb[4] = {bv.x, bv.y, bv.z, bv.w};
            #pragma unroll
            for (int i = 0; i < 8; ++i)
                #pragma unroll
                for (int j = 0; j < 4; ++j)
                    O[i][j] = fmaf(a[i], bb[j], O[i][j]);
        }
    }

    // ---- epilogue: normalize and write ----
    float* outp = OUT + bh * (size_t)(L_ * D_);
    #pragma unroll
    for (int i = 0; i < 8; ++i) {
        float inv = 1.0f / lr[i];
        float4 o = make_float4(O[i][0] * inv, O[i][1] * inv,
                               O[i][2] * inv, O[i][3] * inv);
        *(float4*)(outp + (size_t)(q0 + qrow + i) * D_ + tx * 4) = o;
    }
}

extern "C" void kernel_launch(void* const* d_in, const int* in_sizes, int n_in,
                              void* d_out, int out_size)
{
    const float* Q    = (const float*)d_in[0];
    const float* K    = (const float*)d_in[1];
    const float* V    = (const float*)d_in[2];
    const int*   AM   = (const int*)d_in[3];
    const float* BIAS = (const float*)d_in[4];
    float*       OUT  = (float*)d_out;

    // Idempotent, not a stream op: safe under graph capture, deterministic.
    cudaFuncSetAttribute(SelfAttention_53369263620701_kernel,
                         cudaFuncAttributeMaxDynamicSharedMemorySize, SMEM_BYTES);

    dim3 grid(NQT, H_, B_);   // b slowest -> per-batch bias slice stays L2-resident
    dim3 block(256);
    SelfAttention_53369263620701_kernel<<<grid, block, SMEM_BYTES>>>(
        Q, K, V, AM, BIAS, OUT);
}